// round 10
// baseline (speedup 1.0000x reference)
#include <cuda_runtime.h>
#include <cstdint>

#define MAX_N 100000
#define MAX_E 2000000
#define F 128

// ---------------- device scratch (no allocations allowed) ----------------
__device__ int   g_cnt[MAX_N];             // in-degree (int)
__device__ int   g_off[MAX_N];             // CSR offsets
__device__ int   g_cur[MAX_N];             // fill cursors
__device__ int   g_bsum[1024];             // block sums for scan
__device__ float g_dis[MAX_N];             // deg_inv_sqrt
__device__ int2  g_epack[MAX_E];           // (src, norm bits) grouped by dst
__device__ float g_h  [(size_t)MAX_N * F]; // GEMM output (per layer)
__device__ float g_x2 [(size_t)MAX_N * F]; // layer-1 activation
__device__ int   g_is64;                   // 1 if edge_index is int64

// ---------------- helpers ----------------
__device__ __forceinline__ int load_idx(const void* ei, long long pos) {
    if (g_is64) return (int)((const long long*)ei)[pos];
    return ((const int*)ei)[pos];
}

// ---------------- fused zero + dtype sniff ----------------
__global__ void zero_detect_kernel(const void* ei, int n) {
    int i = blockIdx.x * blockDim.x + threadIdx.x;
    if (i < n) g_cnt[i] = 0;
    if (i == 0) {
        const int* w = (const int*)ei;
        int all_zero = 1;
        // values in [0, 100000): int64 hi-words are 0; false-positive ~0.
        for (int j = 1; j < 64; j += 2) all_zero &= (w[j] == 0);
        g_is64 = all_zero;
    }
}

// ---------------- degree accumulation (dst side, int) ----------------
__global__ void deg_kernel(const void* __restrict__ ei, int E) {
    int i = blockIdx.x * blockDim.x + threadIdx.x;
    if (i >= E) return;
    atomicAdd(&g_cnt[load_idx(ei, (long long)E + i)], 1);
}

// ---------------- scan1 fused with deg_inv_sqrt ----------------
__global__ void scan1_dis_kernel(int n) {
    __shared__ int sm[256];
    int t = threadIdx.x;
    int i = blockIdx.x * 256 + t;
    int v = (i < n) ? g_cnt[i] : 0;
    if (i < n) g_dis[i] = rsqrtf((float)v + 1.0f);
    sm[t] = v;
    __syncthreads();
    for (int off = 128; off > 0; off >>= 1) {
        if (t < off) sm[t] += sm[t + off];
        __syncthreads();
    }
    if (t == 0) g_bsum[blockIdx.x] = sm[0];
}

__global__ void scan2_kernel(int nb) {
    __shared__ int sm[1024];
    int t = threadIdx.x;
    int v = (t < nb) ? g_bsum[t] : 0;
    sm[t] = v;
    __syncthreads();
    for (int off = 1; off < 1024; off <<= 1) {
        int add = (t >= off) ? sm[t - off] : 0;
        __syncthreads();
        sm[t] += add;
        __syncthreads();
    }
    if (t < nb) g_bsum[t] = sm[t] - v;   // exclusive
}

__global__ void scan3_kernel(int n) {
    __shared__ int sm[256];
    int t = threadIdx.x;
    int i = blockIdx.x * 256 + t;
    int v = (i < n) ? g_cnt[i] : 0;
    sm[t] = v;
    __syncthreads();
    for (int off = 1; off < 256; off <<= 1) {
        int add = (t >= off) ? sm[t - off] : 0;
        __syncthreads();
        sm[t] += add;
        __syncthreads();
    }
    if (i < n) {
        int o = g_bsum[blockIdx.x] + sm[t] - v;   // exclusive
        g_off[i] = o;
        g_cur[i] = o;
    }
}

__global__ void fill_kernel(const void* __restrict__ ei, int E) {
    int i = blockIdx.x * blockDim.x + threadIdx.x;
    if (i >= E) return;
    int s = load_idx(ei, i);
    int d = load_idx(ei, (long long)E + i);
    float norm = g_dis[s] * g_dis[d];
    int pos = atomicAdd(&g_cur[d], 1);
    g_epack[pos] = make_int2(s, __float_as_int(norm));
}

// ---------------- GEMM: O[M,128] = X[M,128] @ W[128,128]^T ----------------
// (known-good R5 FFMA kernel: ~15% off the 36 TF/s FFMA roofline)
#define GEMM_TM 64
#define SW_LD 132
__global__ __launch_bounds__(256, 2)
void gemm_kernel(const float* __restrict__ X, const float* __restrict__ W,
                 float* __restrict__ O, int M) {
    extern __shared__ float smem[];
    float* sW = smem;                 // [128][SW_LD] (W transposed)
    float* sX = smem + 128 * SW_LD;   // [64][128]

    int t = threadIdx.x;
    int row0 = blockIdx.x * GEMM_TM;

    for (int idx = t; idx < 128 * 128; idx += 256) {
        int j = idx >> 7, k = idx & 127;
        sW[k * SW_LD + j] = W[idx];
    }
    for (int idx = t; idx < GEMM_TM * 32; idx += 256) {
        int r = idx >> 5, c = idx & 31;
        int gr = row0 + r;
        float4 v = (gr < M) ? ((const float4*)X)[(size_t)gr * 32 + c]
                            : make_float4(0.f, 0.f, 0.f, 0.f);
        ((float4*)sX)[r * 32 + c] = v;
    }
    __syncthreads();

    int tx = t & 31, ty = t >> 5;
    int j0 = tx * 4;

    float acc[8][4];
    #pragma unroll
    for (int rr = 0; rr < 8; rr++)
        #pragma unroll
        for (int c = 0; c < 4; c++) acc[rr][c] = 0.f;

    #pragma unroll 4
    for (int kk = 0; kk < 128; kk += 4) {
        float4 xv[8];
        #pragma unroll
        for (int rr = 0; rr < 8; rr++)
            xv[rr] = *(const float4*)&sX[(ty * 8 + rr) * 128 + kk];
        #pragma unroll
        for (int u = 0; u < 4; u++) {
            float4 w = *(const float4*)&sW[(kk + u) * SW_LD + j0];
            #pragma unroll
            for (int rr = 0; rr < 8; rr++) {
                float xs = (u == 0) ? xv[rr].x : (u == 1) ? xv[rr].y
                         : (u == 2) ? xv[rr].z : xv[rr].w;
                acc[rr][0] += xs * w.x;
                acc[rr][1] += xs * w.y;
                acc[rr][2] += xs * w.z;
                acc[rr][3] += xs * w.w;
            }
        }
    }

    #pragma unroll
    for (int rr = 0; rr < 8; rr++) {
        int gr = row0 + ty * 8 + rr;
        if (gr < M)
            *(float4*)&O[(size_t)gr * 128 + j0] =
                make_float4(acc[rr][0], acc[rr][1], acc[rr][2], acc[rr][3]);
    }
}

// ---------------- fused gather-aggregate + self-loop + bias + leaky ------
// One warp per dst node; 4-edge unroll for MLP; no atomics; one row write.
__global__ __launch_bounds__(256)
void agg_kernel(const float* __restrict__ h, const float* __restrict__ b,
                float* __restrict__ out, int n) {
    int w    = (blockIdx.x * blockDim.x + threadIdx.x) >> 5;
    int lane = threadIdx.x & 31;
    if (w >= n) return;

    int beg = g_off[w];
    int cnt = g_cnt[w];
    const float4* h4 = (const float4*)h;

    float4 acc = make_float4(0.f, 0.f, 0.f, 0.f);

    int e = 0;
    int cnt4 = cnt & ~3;
    for (; e < cnt4; e += 4) {
        int2 p0 = g_epack[beg + e];
        int2 p1 = g_epack[beg + e + 1];
        int2 p2 = g_epack[beg + e + 2];
        int2 p3 = g_epack[beg + e + 3];
        float4 v0 = __ldg(&h4[(size_t)p0.x * 32 + lane]);
        float4 v1 = __ldg(&h4[(size_t)p1.x * 32 + lane]);
        float4 v2 = __ldg(&h4[(size_t)p2.x * 32 + lane]);
        float4 v3 = __ldg(&h4[(size_t)p3.x * 32 + lane]);
        float n0 = __int_as_float(p0.y);
        float n1 = __int_as_float(p1.y);
        float n2 = __int_as_float(p2.y);
        float n3 = __int_as_float(p3.y);
        acc.x += v0.x * n0 + v1.x * n1 + v2.x * n2 + v3.x * n3;
        acc.y += v0.y * n0 + v1.y * n1 + v2.y * n2 + v3.y * n3;
        acc.z += v0.z * n0 + v1.z * n1 + v2.z * n2 + v3.z * n3;
        acc.w += v0.w * n0 + v1.w * n1 + v2.w * n2 + v3.w * n3;
    }
    for (; e < cnt; e++) {
        int2 p0 = g_epack[beg + e];
        float n0 = __int_as_float(p0.y);
        float4 v0 = __ldg(&h4[(size_t)p0.x * 32 + lane]);
        acc.x += v0.x * n0;
        acc.y += v0.y * n0;
        acc.z += v0.z * n0;
        acc.w += v0.w * n0;
    }

    float dis = g_dis[w];
    float sw  = dis * dis;
    float4 hs = __ldg(&h4[(size_t)w * 32 + lane]);
    float4 bb = ((const float4*)b)[lane];
    acc.x += hs.x * sw + bb.x;
    acc.y += hs.y * sw + bb.y;
    acc.z += hs.z * sw + bb.z;
    acc.w += hs.w * sw + bb.w;

    acc.x = (acc.x > 0.f) ? acc.x : 0.01f * acc.x;
    acc.y = (acc.y > 0.f) ? acc.y : 0.01f * acc.y;
    acc.z = (acc.z > 0.f) ? acc.z : 0.01f * acc.z;
    acc.w = (acc.w > 0.f) ? acc.w : 0.01f * acc.w;

    ((float4*)out)[(size_t)w * 32 + lane] = acc;
}

// ---------------- launch ----------------
extern "C" void kernel_launch(void* const* d_in, const int* in_sizes, int n_in,
                              void* d_out, int out_size) {
    const float* x  = (const float*)d_in[0];
    const void*  ei = d_in[1];
    const float* W1 = (const float*)d_in[2];
    const float* b1 = (const float*)d_in[3];
    const float* W2 = (const float*)d_in[4];
    const float* b2 = (const float*)d_in[5];
    float* out = (float*)d_out;

    int n = in_sizes[0] / F;
    int E = in_sizes[1] / 2;

    void *hp_v, *x2p_v;
    cudaGetSymbolAddress(&hp_v,  g_h);
    cudaGetSymbolAddress(&x2p_v, g_x2);
    float* hp  = (float*)hp_v;
    float* x2p = (float*)x2p_v;

    const int gemm_smem = (128 * SW_LD + GEMM_TM * 128) * (int)sizeof(float);
    cudaFuncSetAttribute(gemm_kernel,
                         cudaFuncAttributeMaxDynamicSharedMemorySize, gemm_smem);

    int nb        = (n + 255) / 256;
    int gemm_grid = (n + GEMM_TM - 1) / GEMM_TM;
    int node_grid = (n + 255) / 256;
    int edge_grid = (E + 255) / 256;
    int agg_grid  = ((long long)n * 32 + 255) / 256;

    // Side stream + events for the capture fork/join idiom. Host-side handles
    // only (no device memory); work per call is identical every call.
    static cudaStream_t sB = nullptr;
    static cudaEvent_t  evF = nullptr, evJ = nullptr;
    if (sB == nullptr) {
        cudaStreamCreateWithFlags(&sB, cudaStreamNonBlocking);
        cudaEventCreateWithFlags(&evF, cudaEventDisableTiming);
        cudaEventCreateWithFlags(&evJ, cudaEventDisableTiming);
    }

    // fork: CSR build on sB, concurrent with gemm1 on the main stream
    cudaEventRecord(evF, 0);
    cudaStreamWaitEvent(sB, evF, 0);
    zero_detect_kernel<<<node_grid, 256, 0, sB>>>(ei, n);
    deg_kernel<<<edge_grid, 256, 0, sB>>>(ei, E);
    scan1_dis_kernel<<<nb, 256, 0, sB>>>(n);
    scan2_kernel<<<1, 1024, 0, sB>>>(nb);
    scan3_kernel<<<nb, 256, 0, sB>>>(n);
    fill_kernel<<<edge_grid, 256, 0, sB>>>(ei, E);
    cudaEventRecord(evJ, sB);

    // main stream: layer-1 GEMM overlaps the CSR build
    gemm_kernel<<<gemm_grid, 256, gemm_smem>>>(x, W1, hp, n);

    // join: aggregation needs both gemm1 output and the CSR
    cudaStreamWaitEvent(0, evJ, 0);
    agg_kernel<<<agg_grid, 256>>>(hp, b1, x2p, n);

    // layer 2 (strictly serial)
    gemm_kernel<<<gemm_grid, 256, gemm_smem>>>(x2p, W2, hp, n);
    agg_kernel<<<agg_grid, 256>>>(hp, b2, out, n);
}

// round 11
// speedup vs baseline: 1.5020x; 1.5020x over previous
#include <cuda_runtime.h>
#include <cstdint>

#define MAX_N 100000
#define MAX_E 2000000
#define F 128

// ---------------- device scratch (no allocations allowed) ----------------
__device__ int   g_cnt[MAX_N];             // in-degree (int)
__device__ int   g_off[MAX_N];             // CSR offsets
__device__ int   g_cur[MAX_N];             // fill cursors
__device__ int   g_bsum[1024];             // block sums for scan
__device__ float g_dis[MAX_N];             // deg_inv_sqrt
__device__ int2  g_epack[MAX_E];           // (src, norm bits) grouped by dst
__device__ float g_h  [(size_t)MAX_N * F]; // GEMM output (per layer)
__device__ float g_x2 [(size_t)MAX_N * F]; // layer-1 activation
__device__ int   g_is64;                   // 1 if edge_index is int64

// ---------------- helpers ----------------
__device__ __forceinline__ int load_idx(const void* ei, long long pos) {
    if (g_is64) return (int)((const long long*)ei)[pos];
    return ((const int*)ei)[pos];
}

// ---------------- fused zero + dtype sniff ----------------
__global__ void zero_detect_kernel(const void* ei, int n) {
    int i = blockIdx.x * blockDim.x + threadIdx.x;
    if (i < n) g_cnt[i] = 0;
    if (i == 0) {
        const int* w = (const int*)ei;
        int all_zero = 1;
        // values in [0, 100000): int64 hi-words are 0; false-positive ~0.
        for (int j = 1; j < 64; j += 2) all_zero &= (w[j] == 0);
        g_is64 = all_zero;
    }
}

// ---------------- degree accumulation (dst side, int) ----------------
__global__ void deg_kernel(const void* __restrict__ ei, int E) {
    int i = blockIdx.x * blockDim.x + threadIdx.x;
    if (i >= E) return;
    atomicAdd(&g_cnt[load_idx(ei, (long long)E + i)], 1);
}

// ---------------- scan1 fused with deg_inv_sqrt ----------------
__global__ void scan1_dis_kernel(int n) {
    __shared__ int sm[256];
    int t = threadIdx.x;
    int i = blockIdx.x * 256 + t;
    int v = (i < n) ? g_cnt[i] : 0;
    if (i < n) g_dis[i] = rsqrtf((float)v + 1.0f);
    sm[t] = v;
    __syncthreads();
    for (int off = 128; off > 0; off >>= 1) {
        if (t < off) sm[t] += sm[t + off];
        __syncthreads();
    }
    if (t == 0) g_bsum[blockIdx.x] = sm[0];
}

__global__ void scan2_kernel(int nb) {
    __shared__ int sm[1024];
    int t = threadIdx.x;
    int v = (t < nb) ? g_bsum[t] : 0;
    sm[t] = v;
    __syncthreads();
    for (int off = 1; off < 1024; off <<= 1) {
        int add = (t >= off) ? sm[t - off] : 0;
        __syncthreads();
        sm[t] += add;
        __syncthreads();
    }
    if (t < nb) g_bsum[t] = sm[t] - v;   // exclusive
}

__global__ void scan3_kernel(int n) {
    __shared__ int sm[256];
    int t = threadIdx.x;
    int i = blockIdx.x * 256 + t;
    int v = (i < n) ? g_cnt[i] : 0;
    sm[t] = v;
    __syncthreads();
    for (int off = 1; off < 256; off <<= 1) {
        int add = (t >= off) ? sm[t - off] : 0;
        __syncthreads();
        sm[t] += add;
        __syncthreads();
    }
    if (i < n) {
        int o = g_bsum[blockIdx.x] + sm[t] - v;   // exclusive
        g_off[i] = o;
        g_cur[i] = o;
    }
}

__global__ void fill_kernel(const void* __restrict__ ei, int E) {
    int i = blockIdx.x * blockDim.x + threadIdx.x;
    if (i >= E) return;
    int s = load_idx(ei, i);
    int d = load_idx(ei, (long long)E + i);
    float norm = g_dis[s] * g_dis[d];
    int pos = atomicAdd(&g_cur[d], 1);
    g_epack[pos] = make_int2(s, __float_as_int(norm));
}

// ---------------- GEMM: O[M,128] = X[M,128] @ W[128,128]^T ----------------
// (known-good R5 FFMA kernel: ~15% off the 36 TF/s FFMA roofline)
#define GEMM_TM 64
#define SW_LD 132
__global__ __launch_bounds__(256, 2)
void gemm_kernel(const float* __restrict__ X, const float* __restrict__ W,
                 float* __restrict__ O, int M) {
    extern __shared__ float smem[];
    float* sW = smem;                 // [128][SW_LD] (W transposed)
    float* sX = smem + 128 * SW_LD;   // [64][128]

    int t = threadIdx.x;
    int row0 = blockIdx.x * GEMM_TM;

    for (int idx = t; idx < 128 * 128; idx += 256) {
        int j = idx >> 7, k = idx & 127;
        sW[k * SW_LD + j] = W[idx];
    }
    for (int idx = t; idx < GEMM_TM * 32; idx += 256) {
        int r = idx >> 5, c = idx & 31;
        int gr = row0 + r;
        float4 v = (gr < M) ? ((const float4*)X)[(size_t)gr * 32 + c]
                            : make_float4(0.f, 0.f, 0.f, 0.f);
        ((float4*)sX)[r * 32 + c] = v;
    }
    __syncthreads();

    int tx = t & 31, ty = t >> 5;
    int j0 = tx * 4;

    float acc[8][4];
    #pragma unroll
    for (int rr = 0; rr < 8; rr++)
        #pragma unroll
        for (int c = 0; c < 4; c++) acc[rr][c] = 0.f;

    #pragma unroll 4
    for (int kk = 0; kk < 128; kk += 4) {
        float4 xv[8];
        #pragma unroll
        for (int rr = 0; rr < 8; rr++)
            xv[rr] = *(const float4*)&sX[(ty * 8 + rr) * 128 + kk];
        #pragma unroll
        for (int u = 0; u < 4; u++) {
            float4 w = *(const float4*)&sW[(kk + u) * SW_LD + j0];
            #pragma unroll
            for (int rr = 0; rr < 8; rr++) {
                float xs = (u == 0) ? xv[rr].x : (u == 1) ? xv[rr].y
                         : (u == 2) ? xv[rr].z : xv[rr].w;
                acc[rr][0] += xs * w.x;
                acc[rr][1] += xs * w.y;
                acc[rr][2] += xs * w.z;
                acc[rr][3] += xs * w.w;
            }
        }
    }

    #pragma unroll
    for (int rr = 0; rr < 8; rr++) {
        int gr = row0 + ty * 8 + rr;
        if (gr < M)
            *(float4*)&O[(size_t)gr * 128 + j0] =
                make_float4(acc[rr][0], acc[rr][1], acc[rr][2], acc[rr][3]);
    }
}

// ---------------- fused gather-aggregate + self-loop + bias + leaky ------
// One warp per dst node (exact R5 version: 2-edge unroll, no __ldg).
__global__ __launch_bounds__(256)
void agg_kernel(const float* __restrict__ h, const float* __restrict__ b,
                float* __restrict__ out, int n) {
    int w    = (blockIdx.x * blockDim.x + threadIdx.x) >> 5;
    int lane = threadIdx.x & 31;
    if (w >= n) return;

    int beg = g_off[w];
    int cnt = g_cnt[w];
    const float4* h4 = (const float4*)h;

    float4 acc = make_float4(0.f, 0.f, 0.f, 0.f);

    int e = 0;
    for (; e + 2 <= cnt; e += 2) {
        int2 p0 = g_epack[beg + e];
        int2 p1 = g_epack[beg + e + 1];
        float n0 = __int_as_float(p0.y);
        float n1 = __int_as_float(p1.y);
        float4 v0 = h4[(size_t)p0.x * 32 + lane];
        float4 v1 = h4[(size_t)p1.x * 32 + lane];
        acc.x += v0.x * n0 + v1.x * n1;
        acc.y += v0.y * n0 + v1.y * n1;
        acc.z += v0.z * n0 + v1.z * n1;
        acc.w += v0.w * n0 + v1.w * n1;
    }
    if (e < cnt) {
        int2 p0 = g_epack[beg + e];
        float n0 = __int_as_float(p0.y);
        float4 v0 = h4[(size_t)p0.x * 32 + lane];
        acc.x += v0.x * n0;
        acc.y += v0.y * n0;
        acc.z += v0.z * n0;
        acc.w += v0.w * n0;
    }

    float dis = g_dis[w];
    float sw  = dis * dis;
    float4 hs = h4[(size_t)w * 32 + lane];
    float4 bb = ((const float4*)b)[lane];
    acc.x += hs.x * sw + bb.x;
    acc.y += hs.y * sw + bb.y;
    acc.z += hs.z * sw + bb.z;
    acc.w += hs.w * sw + bb.w;

    acc.x = (acc.x > 0.f) ? acc.x : 0.01f * acc.x;
    acc.y = (acc.y > 0.f) ? acc.y : 0.01f * acc.y;
    acc.z = (acc.z > 0.f) ? acc.z : 0.01f * acc.z;
    acc.w = (acc.w > 0.f) ? acc.w : 0.01f * acc.w;

    ((float4*)out)[(size_t)w * 32 + lane] = acc;
}

// ---------------- launch ----------------
extern "C" void kernel_launch(void* const* d_in, const int* in_sizes, int n_in,
                              void* d_out, int out_size) {
    const float* x  = (const float*)d_in[0];
    const void*  ei = d_in[1];
    const float* W1 = (const float*)d_in[2];
    const float* b1 = (const float*)d_in[3];
    const float* W2 = (const float*)d_in[4];
    const float* b2 = (const float*)d_in[5];
    float* out = (float*)d_out;

    int n = in_sizes[0] / F;
    int E = in_sizes[1] / 2;

    void *hp_v, *x2p_v;
    cudaGetSymbolAddress(&hp_v,  g_h);
    cudaGetSymbolAddress(&x2p_v, g_x2);
    float* hp  = (float*)hp_v;
    float* x2p = (float*)x2p_v;

    const int gemm_smem = (128 * SW_LD + GEMM_TM * 128) * (int)sizeof(float);
    cudaFuncSetAttribute(gemm_kernel,
                         cudaFuncAttributeMaxDynamicSharedMemorySize, gemm_smem);

    int nb        = (n + 255) / 256;
    int gemm_grid = (n + GEMM_TM - 1) / GEMM_TM;
    int node_grid = (n + 255) / 256;
    int edge_grid = (E + 255) / 256;
    int agg_grid  = ((long long)n * 32 + 255) / 256;

    // Single stream. gemm1 has no CSR dependency, so it is interleaved as the
    // 4th launch (the slot ncu's -s window profiles) — next round's profile
    // will show the GEMM roofline instead of a prep kernel.
    zero_detect_kernel<<<node_grid, 256>>>(ei, n);       // 1
    deg_kernel<<<edge_grid, 256>>>(ei, E);               // 2
    scan1_dis_kernel<<<nb, 256>>>(n);                    // 3
    gemm_kernel<<<gemm_grid, 256, gemm_smem>>>(x, W1, hp, n);   // 4 <- profiled
    scan2_kernel<<<1, 1024>>>(nb);                       // 5
    scan3_kernel<<<nb, 256>>>(n);                        // 6
    fill_kernel<<<edge_grid, 256>>>(ei, E);              // 7

    // layer 1 aggregation (needs gemm1 + CSR)
    agg_kernel<<<agg_grid, 256>>>(hp, b1, x2p, n);

    // layer 2
    gemm_kernel<<<gemm_grid, 256, gemm_smem>>>(x2p, W2, hp, n);
    agg_kernel<<<agg_grid, 256>>>(hp, b2, out, n);
}